// round 8
// baseline (speedup 1.0000x reference)
#include <cuda_runtime.h>
#include <math.h>

#define Bb 64
#define Pp 8
#define Nn 4096
#define Dd 256
#define Mm 4096
#define BPc 512
#define EPSC 1e-8f
#define FULLW 0xFFFFFFFFu
#define PINB 24   // batches 0..23 of feats pinned in L2 (96 MB)

// ---- static device scratch ----
__device__ float    g_sim[(size_t)Bb * Nn * Pp];   // raw sim, exp'd in place by k_stats
__device__ float    g_rnorm[Bb * Nn];
__device__ float    g_pn[BPc * Dd];
__device__ unsigned g_max[BPc];
__device__ float    g_zpart[Bb * 4 * Pp];
__device__ int      g_cnt[2][BPc];
__device__ int      g_idx[Bb * Nn];
__device__ float    g_msum[Bb * 16 * Pp];
__device__ float    g_ppart[(size_t)Bb * 16 * Pp * Dd];

typedef unsigned long long u64;

__device__ __forceinline__ void fma2(u64& d, u64 a, u64 b) {
    asm("fma.rn.f32x2 %0, %1, %2, %0;" : "+l"(d) : "l"(a), "l"(b));
}
__device__ __forceinline__ void add2(u64& d, u64 a) {
    asm("add.rn.f32x2 %0, %0, %1;" : "+l"(d) : "l"(a));
}
__device__ __forceinline__ float2 upk(u64 v) {
    float2 r; asm("mov.b64 {%0,%1}, %2;" : "=f"(r.x), "=f"(r.y) : "l"(v)); return r;
}
__device__ __forceinline__ u64 pk(float x, float y) {
    u64 r; asm("mov.b64 %0, {%1,%2};" : "=l"(r) : "f"(x), "f"(y)); return r;
}

// ---- L2 eviction policy via createpolicy + cache_hint (width-agnostic) ----
template<bool PIN>
__device__ __forceinline__ u64 mkpol() {
    u64 p;
    if (PIN)
        asm("createpolicy.fractional.L2::evict_last.b64 %0, 1.0;" : "=l"(p));
    else
        asm("createpolicy.fractional.L2::evict_first.b64 %0, 1.0;" : "=l"(p));
    return p;
}
__device__ __forceinline__ float4 ldg4h(const float4* p, u64 pol) {
    float4 r;
    asm("ld.global.nc.L2::cache_hint.v4.f32 {%0,%1,%2,%3}, [%4], %5;"
        : "=f"(r.x), "=f"(r.y), "=f"(r.z), "=f"(r.w) : "l"(p), "l"(pol));
    return r;
}

__device__ __forceinline__ unsigned f2ord(float f) {
    unsigned u = __float_as_uint(f);
    return (u & 0x80000000u) ? ~u : (u | 0x80000000u);
}
__device__ __forceinline__ float ord2f(unsigned u) {
    return (u & 0x80000000u) ? __uint_as_float(u & 0x7FFFFFFFu) : __uint_as_float(~u);
}

template<bool MX>
__device__ __forceinline__ void red8(float v[8]) {
#pragma unroll
    for (int off = 16; off; off >>= 1) {
#pragma unroll
        for (int p = 0; p < 8; p++) {
            float o = __shfl_xor_sync(FULLW, v[p], off);
            v[p] = MX ? fmaxf(v[p], o) : (v[p] + o);
        }
    }
}

__device__ __forceinline__ float block_sum256(float v, float* r8) {
#pragma unroll
    for (int off = 16; off; off >>= 1) v += __shfl_xor_sync(FULLW, v, off);
    if ((threadIdx.x & 31) == 0) r8[threadIdx.x >> 5] = v;
    __syncthreads();
    if (threadIdx.x == 0) {
        float t = 0.f;
#pragma unroll
        for (int w = 0; w < 8; w++) t += r8[w];
        r8[0] = t;
    }
    __syncthreads();
    return r8[0];
}

// ---- init ----
__global__ void __launch_bounds__(256) k_norm0(const float* __restrict__ pin) {
    __shared__ float r8[8];
    int bp = blockIdx.x, tid = threadIdx.x;
    float v = pin[(size_t)bp * Dd + tid];
    float ss = block_sum256(v * v, r8);
    g_pn[(size_t)bp * Dd + tid] = v / fmaxf(sqrtf(ss), EPSC);
    if (tid == 0) { g_max[bp] = 0u; g_cnt[0][bp] = 0; g_cnt[1][bp] = 0; }
}

// ---- sim pass: R3 staging + packed f32x2 + L2 policy ----
template<bool FIRST, bool DENS, bool PIN>
__global__ void __launch_bounds__(256) k_sim(const float* __restrict__ feats, int bofs) {
    int b = (blockIdx.x >> 4) + bofs, c = blockIdx.x & 15;
    int tid = threadIdx.x, lane = tid & 31, wid = tid >> 5;
    __shared__ float4 pn_s[512];           // 8 KB
    __shared__ float  fs[2][256 * 20];     // 40 KB
    float* red = &fs[0][0];                // overlay after main loop

    u64 pol = mkpol<PIN>();
    const float4* psrc = (const float4*)g_pn + (size_t)b * 512;
    for (int i = tid; i < 512; i += 256) pn_s[i] = psrc[i];

    const float4* fbase = (const float4*)feats + ((size_t)b * Nn + c * 256) * 64;
    int rrow = tid >> 2, rj = tid & 3;
    const float4* gptr[4];
    int soff[4];
#pragma unroll
    for (int k = 0; k < 4; k++) {
        gptr[k] = fbase + (size_t)(k * 64 + rrow) * 64 + rj;
        soff[k] = (k * 64 + rrow) * 20 + rj * 4;
    }

    float4 r0[4];
#pragma unroll
    for (int k = 0; k < 4; k++) r0[k] = ldg4h(gptr[k], pol);
#pragma unroll
    for (int k = 0; k < 4; k++) *(float4*)&fs[0][soff[k]] = r0[k];
    __syncthreads();

    u64 accA[8], accB[8];
#pragma unroll
    for (int p = 0; p < 8; p++) { accA[p] = 0ull; accB[p] = 0ull; }
    u64 sqA = 0ull, sqB = 0ull;

    for (int s = 0; s < 16; s++) {
        int buf = s & 1;
        if (s + 1 < 16) {
#pragma unroll
            for (int k = 0; k < 4; k++) r0[k] = ldg4h(gptr[k] + (s + 1) * 4, pol);
        }
#pragma unroll
        for (int j = 0; j < 4; j++) {
            ulonglong2 f2 = *(const ulonglong2*)&fs[buf][tid * 20 + j * 4];
            if (FIRST) { fma2(sqA, f2.x, f2.x); fma2(sqB, f2.y, f2.y); }
#pragma unroll
            for (int p = 0; p < 8; p++) {
                ulonglong2 q2 = *(const ulonglong2*)&pn_s[p * 64 + s * 4 + j];
                fma2(accA[p], f2.x, q2.x);
                fma2(accB[p], f2.y, q2.y);
            }
        }
        if (s + 1 < 16) {
#pragma unroll
            for (int k = 0; k < 4; k++) *(float4*)&fs[buf ^ 1][soff[k]] = r0[k];
        }
        __syncthreads();
    }

    int n = c * 256 + tid;
    float rn;
    if (FIRST) {
        float2 sa = upk(sqA), sb = upk(sqB);
        float sq = (sa.x + sa.y) + (sb.x + sb.y);
        rn = 1.f / fmaxf(sqrtf(sq), EPSC);
        g_rnorm[b * Nn + n] = rn;
    } else rn = g_rnorm[b * Nn + n];

    float sim[8];
#pragma unroll
    for (int p = 0; p < 8; p++) {
        float2 a = upk(accA[p]), e = upk(accB[p]);
        sim[p] = ((a.x + a.y) + (e.x + e.y)) * rn;
    }
    float4* o = (float4*)(g_sim + ((size_t)b * Nn + n) * 8);
    o[0] = make_float4(sim[0], sim[1], sim[2], sim[3]);
    o[1] = make_float4(sim[4], sim[5], sim[6], sim[7]);

    float mv[8];
#pragma unroll
    for (int p = 0; p < 8; p++) mv[p] = sim[p];
    red8<true>(mv);
    if (lane < 8) red[wid * 8 + lane] = mv[lane];
    __syncthreads();
    if (tid < 8) {
        float m = red[tid];
#pragma unroll
        for (int w = 1; w < 8; w++) m = fmaxf(m, red[w * 8 + tid]);
        atomicMax(&g_max[b * 8 + tid], f2ord(m));
    }

    if (DENS) {
        int a = g_idx[b * Nn + n];
        float dv[8];
#pragma unroll
        for (int p = 0; p < 8; p++) dv[p] = (p == a) ? sim[p] : 0.f;
        red8<false>(dv);
        __syncthreads();
        if (lane < 8) red[wid * 8 + lane] = dv[lane];
        __syncthreads();
        if (tid < 8) {
            float s2 = red[tid];
#pragma unroll
            for (int w = 1; w < 8; w++) s2 += red[w * 8 + tid];
            g_msum[((size_t)b * 16 + c) * 8 + tid] = s2;
        }
    }
}

// ---- stats: tau; exp in place; Z partials ----
template<bool HAS_TAU>
__global__ void __launch_bounds__(256) k_stats(int par) {
    int b = blockIdx.x >> 2, q = blockIdx.x & 3;
    int tid = threadIdx.x, lane = tid & 31, wid = tid >> 5;
    __shared__ float mxs[8], iss[8], red[64];
    if (tid < 8) {
        mxs[tid] = ord2f(g_max[b * 8 + tid]);
        float is;
        if (HAS_TAU) {
            float s = 0.f;
#pragma unroll
            for (int c = 0; c < 16; c++) s += g_msum[((size_t)b * 16 + c) * 8 + tid];
            int cnt = g_cnt[par][b * 8 + tid];
            float mean = s / (float)(cnt >= 1 ? cnt : 1);
            float dens = (cnt >= 1) ? (1.f - mean) : 1.f;
            is = 1.f / (0.1f * fmaxf(dens, 1e-10f));
        } else {
            is = 100.f;
        }
        iss[tid] = is;
    }
    __syncthreads();
    float z[8];
#pragma unroll
    for (int p = 0; p < 8; p++) z[p] = 0.f;
    for (int k = 0; k < 4; k++) {
        int n = q * 1024 + k * 256 + tid;
        float4* p4 = (float4*)(g_sim + ((size_t)b * Nn + n) * 8);
        float4 a = p4[0], c = p4[1];
        a.x = expf((a.x - mxs[0]) * iss[0]); z[0] += a.x;
        a.y = expf((a.y - mxs[1]) * iss[1]); z[1] += a.y;
        a.z = expf((a.z - mxs[2]) * iss[2]); z[2] += a.z;
        a.w = expf((a.w - mxs[3]) * iss[3]); z[3] += a.w;
        c.x = expf((c.x - mxs[4]) * iss[4]); z[4] += c.x;
        c.y = expf((c.y - mxs[5]) * iss[5]); z[5] += c.y;
        c.z = expf((c.z - mxs[6]) * iss[6]); z[6] += c.z;
        c.w = expf((c.w - mxs[7]) * iss[7]); z[7] += c.w;
        p4[0] = a; p4[1] = c;
    }
    red8<false>(z);
    if (lane < 8) red[wid * 8 + lane] = z[lane];
    __syncthreads();
    if (tid < 8) {
        float s = red[tid];
#pragma unroll
        for (int w = 1; w < 8; w++) s += red[w * 8 + tid];
        g_zpart[((size_t)b * 4 + q) * 8 + tid] = s;
    }
}

// ---- update v3: streaming, masked packed weights, quarter-split + L2 policy ----
template<bool PIN>
__global__ void __launch_bounds__(256) k_update(const float* __restrict__ feats,
                                                int parw, int bofs) {
    int b = (blockIdx.x >> 4) + bofs, ch = blockIdx.x & 15;
    int tid = threadIdx.x, lane = tid & 31;
    __shared__ u64  w16[256][8];           // 16 KB
    __shared__ ulonglong2 part[3][8][64];  // 24 KB
    __shared__ float izs[8];

    u64 pol = mkpol<PIN>();
    if (tid < 8) {
        float z = 0.f;
#pragma unroll
        for (int q = 0; q < 4; q++) z += g_zpart[((size_t)b * 4 + q) * 8 + tid];
        izs[tid] = 1.f / z;
    }
    __syncthreads();

    int base = ch * 256;
    {
        const float4* sp = (const float4*)(g_sim + ((size_t)b * Nn + base + tid) * 8);
        float4 e0 = sp[0], e1 = sp[1];
        float w[8] = { e0.x * izs[0], e0.y * izs[1], e0.z * izs[2], e0.w * izs[3],
                       e1.x * izs[4], e1.y * izs[5], e1.z * izs[6], e1.w * izs[7] };
        int bi = 0; float bw = w[0];
#pragma unroll
        for (int p = 1; p < 8; p++) if (w[p] > bw) { bw = w[p]; bi = p; }
        g_idx[b * Nn + base + tid] = bi;
#pragma unroll
        for (int p = 0; p < 8; p++) {
            float wm = (p == bi) ? bw : 0.f;
            w16[tid][p] = pk(wm, wm);
        }
        int mycnt = 0;
#pragma unroll
        for (int p = 0; p < 8; p++) {
            unsigned mk = __ballot_sync(FULLW, bi == p);
            if (lane == p) mycnt += __popc(mk);
        }
        if (lane < 8) atomicAdd(&g_cnt[parw][b * 8 + lane], mycnt);
    }
    __syncthreads();

    int q = tid >> 6;
    int t = tid & 63;
    const float* fb = feats + ((size_t)b * Nn + base + q * 64) * Dd;

    u64 accA[8], accB[8];
#pragma unroll
    for (int p = 0; p < 8; p++) { accA[p] = 0ull; accB[p] = 0ull; }

#pragma unroll 4
    for (int r = 0; r < 64; r++) {
        float4 f = ldg4h((const float4*)(fb + (size_t)r * Dd + 4 * t), pol);
        u64 fx = pk(f.x, f.y), fy = pk(f.z, f.w);
        int row = q * 64 + r;
#pragma unroll
        for (int p = 0; p < 8; p++) {
            u64 wv = w16[row][p];
            fma2(accA[p], wv, fx);
            fma2(accB[p], wv, fy);
        }
    }

    if (q > 0) {
#pragma unroll
        for (int p = 0; p < 8; p++)
            part[q - 1][p][t] = make_ulonglong2(accA[p], accB[p]);
    }
    __syncthreads();

    if (q == 0) {
        float* op = g_ppart + ((size_t)(b * 16 + ch)) * 2048;
#pragma unroll
        for (int p = 0; p < 8; p++) {
#pragma unroll
            for (int qq = 0; qq < 3; qq++) {
                ulonglong2 v = part[qq][p][t];
                add2(accA[p], v.x);
                add2(accB[p], v.y);
            }
            float2 a = upk(accA[p]), e = upk(accB[p]);
            *(float4*)(op + p * 256 + 4 * t) = make_float4(a.x, a.y, e.x, e.y);
        }
    }
}

// ---- reduce 16 partials -> prototypes; normalize; reset state ----
__global__ void __launch_bounds__(256) k_reduce(float* __restrict__ outp, int parzero) {
    __shared__ float r8[8];
    int bp = blockIdx.x, b = bp >> 3, p = bp & 7;
    int tid = threadIdx.x;
    float v = 0.f;
#pragma unroll
    for (int c = 0; c < 16; c++)
        v += g_ppart[((size_t)(b * 16 + c)) * 2048 + p * 256 + tid];
    float ss = block_sum256(v * v, r8);
    float rn = 1.f / fmaxf(sqrtf(ss), EPSC);
    outp[(size_t)bp * Dd + tid] = v;
    g_pn[(size_t)bp * Dd + tid] = v * rn;
    if (tid == 0) { g_max[bp] = 0u; g_cnt[parzero][bp] = 0; }
}

// ---- final sim_map ----
__global__ void __launch_bounds__(256) k_simmap(const float* __restrict__ forg,
                                                float* __restrict__ out) {
    int b = blockIdx.x >> 4, c = blockIdx.x & 15;
    int tid = threadIdx.x;
    __shared__ float4 pn_s[512];
    __shared__ float  fs[2][256 * 20];

    const float4* psrc = (const float4*)g_pn + (size_t)b * 512;
    for (int i = tid; i < 512; i += 256) pn_s[i] = psrc[i];

    const float4* fbase = (const float4*)forg + (size_t)c * 256 * 64;
    int rrow = tid >> 2, rj = tid & 3;
    const float4* gptr[4];
    int soff[4];
#pragma unroll
    for (int k = 0; k < 4; k++) {
        gptr[k] = fbase + (size_t)(k * 64 + rrow) * 64 + rj;
        soff[k] = (k * 64 + rrow) * 20 + rj * 4;
    }
    float4 r0[4];
#pragma unroll
    for (int k = 0; k < 4; k++) r0[k] = gptr[k][0];
#pragma unroll
    for (int k = 0; k < 4; k++) *(float4*)&fs[0][soff[k]] = r0[k];
    __syncthreads();

    u64 accA[8], accB[8];
#pragma unroll
    for (int p = 0; p < 8; p++) { accA[p] = 0ull; accB[p] = 0ull; }
    u64 sqA = 0ull, sqB = 0ull;

    for (int s = 0; s < 16; s++) {
        int buf = s & 1;
        if (s + 1 < 16) {
#pragma unroll
            for (int k = 0; k < 4; k++) r0[k] = gptr[k][(s + 1) * 4];
        }
#pragma unroll
        for (int j = 0; j < 4; j++) {
            ulonglong2 f2 = *(const ulonglong2*)&fs[buf][tid * 20 + j * 4];
            fma2(sqA, f2.x, f2.x); fma2(sqB, f2.y, f2.y);
#pragma unroll
            for (int p = 0; p < 8; p++) {
                ulonglong2 q2 = *(const ulonglong2*)&pn_s[p * 64 + s * 4 + j];
                fma2(accA[p], f2.x, q2.x);
                fma2(accB[p], f2.y, q2.y);
            }
        }
        if (s + 1 < 16) {
#pragma unroll
            for (int k = 0; k < 4; k++) *(float4*)&fs[buf ^ 1][soff[k]] = r0[k];
        }
        __syncthreads();
    }
    int m = c * 256 + tid;
    float2 sa = upk(sqA), sb = upk(sqB);
    float sq = (sa.x + sa.y) + (sb.x + sb.y);
    float rn = 1.f / fmaxf(sqrtf(sq), EPSC);
#pragma unroll
    for (int p = 0; p < 8; p++) {
        float2 a = upk(accA[p]), e = upk(accB[p]);
        out[((size_t)b * Pp + p) * Mm + m] = ((a.x + a.y) + (e.x + e.y)) * rn;
    }
}

extern "C" void kernel_launch(void* const* d_in, const int* in_sizes, int n_in,
                              void* d_out, int out_size) {
    const float* protos = (const float*)d_in[0];
    const float* feats  = (const float*)d_in[1];
    const float* forg   = (const float*)d_in[2];
    float* out = (float*)d_out;

    k_norm0<<<BPc, 256>>>(protos);

    k_sim<true, false, true ><<<PINB * 16, 256>>>(feats, 0);
    k_sim<true, false, false><<<(Bb - PINB) * 16, 256>>>(feats, PINB);
    k_stats<false><<<Bb * 4, 256>>>(0);
    k_update<true ><<<PINB * 16, 256>>>(feats, 0, 0);
    k_update<false><<<(Bb - PINB) * 16, 256>>>(feats, 0, PINB);
    k_reduce<<<BPc, 256>>>(out, 1);

    for (int t = 1; t < 5; t++) {
        k_sim<false, true, true ><<<PINB * 16, 256>>>(feats, 0);
        k_sim<false, true, false><<<(Bb - PINB) * 16, 256>>>(feats, PINB);
        k_stats<true><<<Bb * 4, 256>>>((t - 1) & 1);
        k_update<true ><<<PINB * 16, 256>>>(feats, t & 1, 0);
        k_update<false><<<(Bb - PINB) * 16, 256>>>(feats, t & 1, PINB);
        k_reduce<<<BPc, 256>>>(out, (t + 1) & 1);
    }

    k_simmap<<<Bb * 16, 256>>>(forg, out + (size_t)BPc * Dd);
}

// round 9
// speedup vs baseline: 1.2288x; 1.2288x over previous
#include <cuda_runtime.h>
#include <math.h>

#define Bb 64
#define Pp 8
#define Nn 4096
#define Dd 256
#define Mm 4096
#define BPc 512
#define EPSC 1e-8f
#define FULLW 0xFFFFFFFFu
#define PINB 24   // batches 0..23 of feats L2-pinned (96 MB)

// ---- static device scratch ----
__device__ float    g_sim[(size_t)Bb * Nn * Pp];   // raw sim, exp'd in place by k_stats
__device__ float    g_rnorm[Bb * Nn];
__device__ float    g_pn[BPc * Dd];
__device__ unsigned g_max[BPc];
__device__ float    g_zpart[Bb * 4 * Pp];
__device__ int      g_cnt[2][BPc];
__device__ int      g_idx[Bb * Nn];
__device__ float    g_msum[Bb * 16 * Pp];
__device__ float    g_ppart[(size_t)Bb * 16 * Pp * Dd];

typedef unsigned long long u64;

__device__ __forceinline__ void fma2(u64& d, u64 a, u64 b) {
    asm("fma.rn.f32x2 %0, %1, %2, %0;" : "+l"(d) : "l"(a), "l"(b));
}
__device__ __forceinline__ void add2(u64& d, u64 a) {
    asm("add.rn.f32x2 %0, %0, %1;" : "+l"(d) : "l"(a));
}
__device__ __forceinline__ float2 upk(u64 v) {
    float2 r; asm("mov.b64 {%0,%1}, %2;" : "=f"(r.x), "=f"(r.y) : "l"(v)); return r;
}
__device__ __forceinline__ u64 pk(float x, float y) {
    u64 r; asm("mov.b64 %0, {%1,%2};" : "=l"(r) : "f"(x), "f"(y)); return r;
}

// ---- L2 eviction policy via createpolicy + cache_hint ----
__device__ __forceinline__ u64 mkpol_rt(bool pin) {
    u64 p;
    if (pin)
        asm("createpolicy.fractional.L2::evict_last.b64 %0, 1.0;" : "=l"(p));
    else
        asm("createpolicy.fractional.L2::evict_first.b64 %0, 1.0;" : "=l"(p));
    return p;
}
__device__ __forceinline__ float4 ldg4h(const float4* p, u64 pol) {
    float4 r;
    asm("ld.global.nc.L2::cache_hint.v4.f32 {%0,%1,%2,%3}, [%4], %5;"
        : "=f"(r.x), "=f"(r.y), "=f"(r.z), "=f"(r.w) : "l"(p), "l"(pol));
    return r;
}
__device__ __forceinline__ u64 ldg64h(const void* p, u64 pol) {
    u64 r;
    asm("ld.global.nc.L2::cache_hint.b64 %0, [%1], %2;"
        : "=l"(r) : "l"(p), "l"(pol));
    return r;
}

__device__ __forceinline__ unsigned f2ord(float f) {
    unsigned u = __float_as_uint(f);
    return (u & 0x80000000u) ? ~u : (u | 0x80000000u);
}
__device__ __forceinline__ float ord2f(unsigned u) {
    return (u & 0x80000000u) ? __uint_as_float(u & 0x7FFFFFFFu) : __uint_as_float(~u);
}

template<bool MX>
__device__ __forceinline__ void red8(float v[8]) {
#pragma unroll
    for (int off = 16; off; off >>= 1) {
#pragma unroll
        for (int p = 0; p < 8; p++) {
            float o = __shfl_xor_sync(FULLW, v[p], off);
            v[p] = MX ? fmaxf(v[p], o) : (v[p] + o);
        }
    }
}

__device__ __forceinline__ float block_sum256(float v, float* r8) {
#pragma unroll
    for (int off = 16; off; off >>= 1) v += __shfl_xor_sync(FULLW, v, off);
    if ((threadIdx.x & 31) == 0) r8[threadIdx.x >> 5] = v;
    __syncthreads();
    if (threadIdx.x == 0) {
        float t = 0.f;
#pragma unroll
        for (int w = 0; w < 8; w++) t += r8[w];
        r8[0] = t;
    }
    __syncthreads();
    return r8[0];
}

// ---- init ----
__global__ void __launch_bounds__(256) k_norm0(const float* __restrict__ pin) {
    __shared__ float r8[8];
    int bp = blockIdx.x, tid = threadIdx.x;
    float v = pin[(size_t)bp * Dd + tid];
    float ss = block_sum256(v * v, r8);
    g_pn[(size_t)bp * Dd + tid] = v / fmaxf(sqrtf(ss), EPSC);
    if (tid == 0) { g_max[bp] = 0u; g_cnt[0][bp] = 0; g_cnt[1][bp] = 0; }
}

// ---- sim pass: R3 staging + packed f32x2 + runtime L2 policy ----
template<bool FIRST, bool DENS>
__global__ void __launch_bounds__(256) k_sim(const float* __restrict__ feats) {
    int b = blockIdx.x >> 4, c = blockIdx.x & 15;
    int tid = threadIdx.x, lane = tid & 31, wid = tid >> 5;
    __shared__ float4 pn_s[512];           // 8 KB
    __shared__ float  fs[2][256 * 20];     // 40 KB
    float* red = &fs[0][0];                // overlay after main loop

    u64 pol = mkpol_rt(b < PINB);
    const float4* psrc = (const float4*)g_pn + (size_t)b * 512;
    for (int i = tid; i < 512; i += 256) pn_s[i] = psrc[i];

    const float4* fbase = (const float4*)feats + ((size_t)b * Nn + c * 256) * 64;
    int rrow = tid >> 2, rj = tid & 3;
    const float4* gptr[4];
    int soff[4];
#pragma unroll
    for (int k = 0; k < 4; k++) {
        gptr[k] = fbase + (size_t)(k * 64 + rrow) * 64 + rj;
        soff[k] = (k * 64 + rrow) * 20 + rj * 4;
    }

    float4 r0[4];
#pragma unroll
    for (int k = 0; k < 4; k++) r0[k] = ldg4h(gptr[k], pol);
#pragma unroll
    for (int k = 0; k < 4; k++) *(float4*)&fs[0][soff[k]] = r0[k];
    __syncthreads();

    u64 accA[8], accB[8];
#pragma unroll
    for (int p = 0; p < 8; p++) { accA[p] = 0ull; accB[p] = 0ull; }
    u64 sqA = 0ull, sqB = 0ull;

    for (int s = 0; s < 16; s++) {
        int buf = s & 1;
        if (s + 1 < 16) {
#pragma unroll
            for (int k = 0; k < 4; k++) r0[k] = ldg4h(gptr[k] + (s + 1) * 4, pol);
        }
#pragma unroll
        for (int j = 0; j < 4; j++) {
            ulonglong2 f2 = *(const ulonglong2*)&fs[buf][tid * 20 + j * 4];
            if (FIRST) { fma2(sqA, f2.x, f2.x); fma2(sqB, f2.y, f2.y); }
#pragma unroll
            for (int p = 0; p < 8; p++) {
                ulonglong2 q2 = *(const ulonglong2*)&pn_s[p * 64 + s * 4 + j];
                fma2(accA[p], f2.x, q2.x);
                fma2(accB[p], f2.y, q2.y);
            }
        }
        if (s + 1 < 16) {
#pragma unroll
            for (int k = 0; k < 4; k++) *(float4*)&fs[buf ^ 1][soff[k]] = r0[k];
        }
        __syncthreads();
    }

    int n = c * 256 + tid;
    float rn;
    if (FIRST) {
        float2 sa = upk(sqA), sb = upk(sqB);
        float sq = (sa.x + sa.y) + (sb.x + sb.y);
        rn = 1.f / fmaxf(sqrtf(sq), EPSC);
        g_rnorm[b * Nn + n] = rn;
    } else rn = g_rnorm[b * Nn + n];

    float sim[8];
#pragma unroll
    for (int p = 0; p < 8; p++) {
        float2 a = upk(accA[p]), e = upk(accB[p]);
        sim[p] = ((a.x + a.y) + (e.x + e.y)) * rn;
    }
    float4* o = (float4*)(g_sim + ((size_t)b * Nn + n) * 8);
    o[0] = make_float4(sim[0], sim[1], sim[2], sim[3]);
    o[1] = make_float4(sim[4], sim[5], sim[6], sim[7]);

    float mv[8];
#pragma unroll
    for (int p = 0; p < 8; p++) mv[p] = sim[p];
    red8<true>(mv);
    if (lane < 8) red[wid * 8 + lane] = mv[lane];
    __syncthreads();
    if (tid < 8) {
        float m = red[tid];
#pragma unroll
        for (int w = 1; w < 8; w++) m = fmaxf(m, red[w * 8 + tid]);
        atomicMax(&g_max[b * 8 + tid], f2ord(m));
    }

    if (DENS) {
        int a = g_idx[b * Nn + n];
        float dv[8];
#pragma unroll
        for (int p = 0; p < 8; p++) dv[p] = (p == a) ? sim[p] : 0.f;
        red8<false>(dv);
        __syncthreads();
        if (lane < 8) red[wid * 8 + lane] = dv[lane];
        __syncthreads();
        if (tid < 8) {
            float s2 = red[tid];
#pragma unroll
            for (int w = 1; w < 8; w++) s2 += red[w * 8 + tid];
            g_msum[((size_t)b * 16 + c) * 8 + tid] = s2;
        }
    }
}

// ---- stats: tau; exp in place; Z partials ----
template<bool HAS_TAU>
__global__ void __launch_bounds__(256) k_stats(int par) {
    int b = blockIdx.x >> 2, q = blockIdx.x & 3;
    int tid = threadIdx.x, lane = tid & 31, wid = tid >> 5;
    __shared__ float mxs[8], iss[8], red[64];
    if (tid < 8) {
        mxs[tid] = ord2f(g_max[b * 8 + tid]);
        float is;
        if (HAS_TAU) {
            float s = 0.f;
#pragma unroll
            for (int c = 0; c < 16; c++) s += g_msum[((size_t)b * 16 + c) * 8 + tid];
            int cnt = g_cnt[par][b * 8 + tid];
            float mean = s / (float)(cnt >= 1 ? cnt : 1);
            float dens = (cnt >= 1) ? (1.f - mean) : 1.f;
            is = 1.f / (0.1f * fmaxf(dens, 1e-10f));
        } else {
            is = 100.f;
        }
        iss[tid] = is;
    }
    __syncthreads();
    float z[8];
#pragma unroll
    for (int p = 0; p < 8; p++) z[p] = 0.f;
    for (int k = 0; k < 4; k++) {
        int n = q * 1024 + k * 256 + tid;
        float4* p4 = (float4*)(g_sim + ((size_t)b * Nn + n) * 8);
        float4 a = p4[0], c = p4[1];
        a.x = expf((a.x - mxs[0]) * iss[0]); z[0] += a.x;
        a.y = expf((a.y - mxs[1]) * iss[1]); z[1] += a.y;
        a.z = expf((a.z - mxs[2]) * iss[2]); z[2] += a.z;
        a.w = expf((a.w - mxs[3]) * iss[3]); z[3] += a.w;
        c.x = expf((c.x - mxs[4]) * iss[4]); z[4] += c.x;
        c.y = expf((c.y - mxs[5]) * iss[5]); z[5] += c.y;
        c.z = expf((c.z - mxs[6]) * iss[6]); z[6] += c.z;
        c.w = expf((c.w - mxs[7]) * iss[7]); z[7] += c.w;
        p4[0] = a; p4[1] = c;
    }
    red8<false>(z);
    if (lane < 8) red[wid * 8 + lane] = z[lane];
    __syncthreads();
    if (tid < 8) {
        float s = red[tid];
#pragma unroll
        for (int w = 1; w < 8; w++) s += red[w * 8 + tid];
        g_zpart[((size_t)b * 4 + q) * 8 + tid] = s;
    }
}

// ---- update v4: 2 cols/thread, batched LDG.64, uniform branch tree ----
__global__ void __launch_bounds__(256) k_update(const float* __restrict__ feats,
                                                int parw) {
    int b = blockIdx.x >> 4, ch = blockIdx.x & 15;
    int tid = threadIdx.x, lane = tid & 31;
    __shared__ float ws[256];
    __shared__ int   bis[256];
    __shared__ u64   part[8][128];   // 8 KB: group-1 partials
    __shared__ float izs[8];

    u64 pol = mkpol_rt(b < PINB);
    if (tid < 8) {
        float z = 0.f;
#pragma unroll
        for (int q = 0; q < 4; q++) z += g_zpart[((size_t)b * 4 + q) * 8 + tid];
        izs[tid] = 1.f / z;
    }
    __syncthreads();

    int base = ch * 256;
    // ---- phase 1: row tid -> weight + argmax ----
    {
        const float4* sp = (const float4*)(g_sim + ((size_t)b * Nn + base + tid) * 8);
        float4 e0 = sp[0], e1 = sp[1];
        float w[8] = { e0.x * izs[0], e0.y * izs[1], e0.z * izs[2], e0.w * izs[3],
                       e1.x * izs[4], e1.y * izs[5], e1.z * izs[6], e1.w * izs[7] };
        int bi = 0; float bw = w[0];
#pragma unroll
        for (int p = 1; p < 8; p++) if (w[p] > bw) { bw = w[p]; bi = p; }
        g_idx[b * Nn + base + tid] = bi;
        ws[tid] = bw;
        bis[tid] = bi;
        int mycnt = 0;
#pragma unroll
        for (int p = 0; p < 8; p++) {
            unsigned mk = __ballot_sync(FULLW, bi == p);
            if (lane == p) mycnt += __popc(mk);
        }
        if (lane < 8) atomicAdd(&g_cnt[parw][b * 8 + lane], mycnt);
    }
    __syncthreads();

    // ---- phase 2: group g2 streams 128 rows; thread owns cols 2t, 2t+1 ----
    int g2 = tid >> 7;
    int t = tid & 127;
    const float* fb = feats + ((size_t)b * Nn + base + g2 * 128) * Dd;

    u64 acc[8];
#pragma unroll
    for (int p = 0; p < 8; p++) acc[p] = 0ull;

    for (int r0 = 0; r0 < 128; r0 += 8) {
        u64 f[8];
#pragma unroll
        for (int k = 0; k < 8; k++)
            f[k] = ldg64h(fb + (size_t)(r0 + k) * Dd + 2 * t, pol);
#pragma unroll
        for (int k = 0; k < 8; k++) {
            int row = (g2 << 7) + r0 + k;
            float wv = ws[row];
            int bi = bis[row];           // uniform across the warp
            u64 wp = pk(wv, wv);
            if (bi < 4) {
                if (bi < 2) { if (bi == 0) fma2(acc[0], wp, f[k]); else fma2(acc[1], wp, f[k]); }
                else        { if (bi == 2) fma2(acc[2], wp, f[k]); else fma2(acc[3], wp, f[k]); }
            } else {
                if (bi < 6) { if (bi == 4) fma2(acc[4], wp, f[k]); else fma2(acc[5], wp, f[k]); }
                else        { if (bi == 6) fma2(acc[6], wp, f[k]); else fma2(acc[7], wp, f[k]); }
            }
        }
    }

    if (g2 == 1) {
#pragma unroll
        for (int p = 0; p < 8; p++) part[p][t] = acc[p];
    }
    __syncthreads();
    if (g2 == 0) {
        float* op = g_ppart + ((size_t)(b * 16 + ch)) * 2048;
#pragma unroll
        for (int p = 0; p < 8; p++) {
            add2(acc[p], part[p][t]);
            float2 a = upk(acc[p]);
            *(float2*)(op + p * 256 + 2 * t) = a;
        }
    }
}

// ---- reduce 16 partials -> prototypes; normalize; reset state ----
__global__ void __launch_bounds__(256) k_reduce(float* __restrict__ outp, int parzero) {
    __shared__ float r8[8];
    int bp = blockIdx.x, b = bp >> 3, p = bp & 7;
    int tid = threadIdx.x;
    float v = 0.f;
#pragma unroll
    for (int c = 0; c < 16; c++)
        v += g_ppart[((size_t)(b * 16 + c)) * 2048 + p * 256 + tid];
    float ss = block_sum256(v * v, r8);
    float rn = 1.f / fmaxf(sqrtf(ss), EPSC);
    outp[(size_t)bp * Dd + tid] = v;
    g_pn[(size_t)bp * Dd + tid] = v * rn;
    if (tid == 0) { g_max[bp] = 0u; g_cnt[parzero][bp] = 0; }
}

// ---- final sim_map ----
__global__ void __launch_bounds__(256) k_simmap(const float* __restrict__ forg,
                                                float* __restrict__ out) {
    int b = blockIdx.x >> 4, c = blockIdx.x & 15;
    int tid = threadIdx.x;
    __shared__ float4 pn_s[512];
    __shared__ float  fs[2][256 * 20];

    const float4* psrc = (const float4*)g_pn + (size_t)b * 512;
    for (int i = tid; i < 512; i += 256) pn_s[i] = psrc[i];

    const float4* fbase = (const float4*)forg + (size_t)c * 256 * 64;
    int rrow = tid >> 2, rj = tid & 3;
    const float4* gptr[4];
    int soff[4];
#pragma unroll
    for (int k = 0; k < 4; k++) {
        gptr[k] = fbase + (size_t)(k * 64 + rrow) * 64 + rj;
        soff[k] = (k * 64 + rrow) * 20 + rj * 4;
    }
    float4 r0[4];
#pragma unroll
    for (int k = 0; k < 4; k++) r0[k] = gptr[k][0];
#pragma unroll
    for (int k = 0; k < 4; k++) *(float4*)&fs[0][soff[k]] = r0[k];
    __syncthreads();

    u64 accA[8], accB[8];
#pragma unroll
    for (int p = 0; p < 8; p++) { accA[p] = 0ull; accB[p] = 0ull; }
    u64 sqA = 0ull, sqB = 0ull;

    for (int s = 0; s < 16; s++) {
        int buf = s & 1;
        if (s + 1 < 16) {
#pragma unroll
            for (int k = 0; k < 4; k++) r0[k] = gptr[k][(s + 1) * 4];
        }
#pragma unroll
        for (int j = 0; j < 4; j++) {
            ulonglong2 f2 = *(const ulonglong2*)&fs[buf][tid * 20 + j * 4];
            fma2(sqA, f2.x, f2.x); fma2(sqB, f2.y, f2.y);
#pragma unroll
            for (int p = 0; p < 8; p++) {
                ulonglong2 q2 = *(const ulonglong2*)&pn_s[p * 64 + s * 4 + j];
                fma2(accA[p], f2.x, q2.x);
                fma2(accB[p], f2.y, q2.y);
            }
        }
        if (s + 1 < 16) {
#pragma unroll
            for (int k = 0; k < 4; k++) *(float4*)&fs[buf ^ 1][soff[k]] = r0[k];
        }
        __syncthreads();
    }
    int m = c * 256 + tid;
    float2 sa = upk(sqA), sb = upk(sqB);
    float sq = (sa.x + sa.y) + (sb.x + sb.y);
    float rn = 1.f / fmaxf(sqrtf(sq), EPSC);
#pragma unroll
    for (int p = 0; p < 8; p++) {
        float2 a = upk(accA[p]), e = upk(accB[p]);
        out[((size_t)b * Pp + p) * Mm + m] = ((a.x + a.y) + (e.x + e.y)) * rn;
    }
}

extern "C" void kernel_launch(void* const* d_in, const int* in_sizes, int n_in,
                              void* d_out, int out_size) {
    const float* protos = (const float*)d_in[0];
    const float* feats  = (const float*)d_in[1];
    const float* forg   = (const float*)d_in[2];
    float* out = (float*)d_out;

    k_norm0<<<BPc, 256>>>(protos);

    k_sim<true, false><<<Bb * 16, 256>>>(feats);
    k_stats<false><<<Bb * 4, 256>>>(0);
    k_update<<<Bb * 16, 256>>>(feats, 0);
    k_reduce<<<BPc, 256>>>(out, 1);

    for (int t = 1; t < 5; t++) {
        k_sim<false, true><<<Bb * 16, 256>>>(feats);
        k_stats<true><<<Bb * 4, 256>>>((t - 1) & 1);
        k_update<<<Bb * 16, 256>>>(feats, t & 1);
        k_reduce<<<BPc, 256>>>(out, (t + 1) & 1);
    }

    k_simmap<<<Bb * 16, 256>>>(forg, out + (size_t)BPc * Dd);
}

// round 10
// speedup vs baseline: 1.4841x; 1.2078x over previous
#include <cuda_runtime.h>
#include <math.h>

#define Bb 64
#define Pp 8
#define Nn 4096
#define Dd 256
#define Mm 4096
#define BPc 512
#define EPSC 1e-8f
#define FULLW 0xFFFFFFFFu
#define PINB 24

// ---- static device scratch ----
__device__ float    g_sim[(size_t)Bb * Nn * Pp];   // raw sim, exp'd in place by k_stats
__device__ float    g_rnorm[Bb * Nn];
__device__ float    g_pn[BPc * Dd];
__device__ unsigned g_max[BPc];
__device__ float    g_zpart[Bb * 4 * Pp];
__device__ int      g_cnt[2][BPc];
__device__ int      g_idx[Bb * Nn];
__device__ float    g_msum[Bb * 16 * Pp];
__device__ float    g_ppart[(size_t)Bb * 16 * Pp * Dd];

typedef unsigned long long u64;

__device__ __forceinline__ void fma2(u64& d, u64 a, u64 b) {
    asm("fma.rn.f32x2 %0, %1, %2, %0;" : "+l"(d) : "l"(a), "l"(b));
}
__device__ __forceinline__ void add2(u64& d, u64 a) {
    asm("add.rn.f32x2 %0, %0, %1;" : "+l"(d) : "l"(a));
}
__device__ __forceinline__ float2 upk(u64 v) {
    float2 r; asm("mov.b64 {%0,%1}, %2;" : "=f"(r.x), "=f"(r.y) : "l"(v)); return r;
}
__device__ __forceinline__ u64 pk(float x, float y) {
    u64 r; asm("mov.b64 %0, {%1,%2};" : "=l"(r) : "f"(x), "f"(y)); return r;
}

__device__ __forceinline__ u64 mkpol_rt(bool pin) {
    u64 p;
    if (pin)
        asm("createpolicy.fractional.L2::evict_last.b64 %0, 1.0;" : "=l"(p));
    else
        asm("createpolicy.fractional.L2::evict_first.b64 %0, 1.0;" : "=l"(p));
    return p;
}
__device__ __forceinline__ u64 ldg64h(const void* p, u64 pol) {
    u64 r;
    asm("ld.global.nc.L2::cache_hint.b64 %0, [%1], %2;"
        : "=l"(r) : "l"(p), "l"(pol));
    return r;
}

// ---- cp.async helpers ----
__device__ __forceinline__ void cpa16(unsigned dst, const void* src) {
    asm volatile("cp.async.cg.shared.global [%0], [%1], 16;" :: "r"(dst), "l"(src));
}
__device__ __forceinline__ void cpcommit() { asm volatile("cp.async.commit_group;"); }
__device__ __forceinline__ void cpwait2() { asm volatile("cp.async.wait_group 2;"); }

__device__ __forceinline__ unsigned f2ord(float f) {
    unsigned u = __float_as_uint(f);
    return (u & 0x80000000u) ? ~u : (u | 0x80000000u);
}
__device__ __forceinline__ float ord2f(unsigned u) {
    return (u & 0x80000000u) ? __uint_as_float(u & 0x7FFFFFFFu) : __uint_as_float(~u);
}

template<bool MX>
__device__ __forceinline__ void red8(float v[8]) {
#pragma unroll
    for (int off = 16; off; off >>= 1) {
#pragma unroll
        for (int p = 0; p < 8; p++) {
            float o = __shfl_xor_sync(FULLW, v[p], off);
            v[p] = MX ? fmaxf(v[p], o) : (v[p] + o);
        }
    }
}

__device__ __forceinline__ float block_sum256(float v, float* r8) {
#pragma unroll
    for (int off = 16; off; off >>= 1) v += __shfl_xor_sync(FULLW, v, off);
    if ((threadIdx.x & 31) == 0) r8[threadIdx.x >> 5] = v;
    __syncthreads();
    if (threadIdx.x == 0) {
        float t = 0.f;
#pragma unroll
        for (int w = 0; w < 8; w++) t += r8[w];
        r8[0] = t;
    }
    __syncthreads();
    return r8[0];
}

// ---- init ----
__global__ void __launch_bounds__(256) k_norm0(const float* __restrict__ pin) {
    __shared__ float r8[8];
    int bp = blockIdx.x, tid = threadIdx.x;
    float v = pin[(size_t)bp * Dd + tid];
    float ss = block_sum256(v * v, r8);
    g_pn[(size_t)bp * Dd + tid] = v / fmaxf(sqrtf(ss), EPSC);
    if (tid == 0) { g_max[bp] = 0u; g_cnt[0][bp] = 0; g_cnt[1][bp] = 0; }
}

// ---- sim pass: 4-stage cp.async ring, 1 sync/stage, XOR-swizzled tiles ----
// dyn smem: pn_s 8192 | fs 4*16384 | red 256 = 73984 B  -> 3 CTAs/SM
#define SIMSMEM (8192 + 4 * 16384 + 256)

template<bool FIRST, bool DENS>
__global__ void __launch_bounds__(256) k_sim(const float* __restrict__ feats) {
    extern __shared__ char smraw[];
    float4* pn_s = (float4*)smraw;
    float*  fs   = (float*)(smraw + 8192);
    float*  red  = (float*)(smraw + 8192 + 4 * 16384);

    int b = blockIdx.x >> 4, c = blockIdx.x & 15;
    int tid = threadIdx.x, lane = tid & 31, wid = tid >> 5;

    const float4* psrc = (const float4*)g_pn + (size_t)b * 512;
    for (int i = tid; i < 512; i += 256) pn_s[i] = psrc[i];

    const float* fbase = feats + ((size_t)b * Nn + c * 256) * Dd;
    int r0 = tid >> 2, j = tid & 3;
    unsigned fsb = (unsigned)__cvta_generic_to_shared(fs);

    // prologue: stages 0..2 in flight
#pragma unroll
    for (int s = 0; s < 3; s++) {
#pragma unroll
        for (int k = 0; k < 4; k++) {
            int row = r0 + 64 * k;
            int jc = j ^ (row & 3);
            cpa16(fsb + (s << 14) + row * 64 + jc * 16,
                  fbase + (size_t)row * Dd + s * 16 + j * 4);
        }
        cpcommit();
    }

    u64 acc[8];
#pragma unroll
    for (int p = 0; p < 8; p++) acc[p] = 0ull;
    u64 sq = 0ull;
    int sw = tid & 3;

    for (int s = 0; s < 16; s++) {
        cpwait2();
        __syncthreads();
        const float* fb = fs + ((s & 3) << 12);
#pragma unroll
        for (int jj = 0; jj < 4; jj++) {
            // physical chunk (jj^sw) holds logical chunk jj for row tid
            ulonglong2 f2 = *(const ulonglong2*)&fb[tid * 16 + ((jj ^ sw) << 2)];
            if (FIRST) { fma2(sq, f2.x, f2.x); fma2(sq, f2.y, f2.y); }
#pragma unroll
            for (int p = 0; p < 8; p++) {
                ulonglong2 q2 = *(const ulonglong2*)(pn_s + p * 64 + s * 4 + jj);
                fma2(acc[p], f2.x, q2.x);
                fma2(acc[p], f2.y, q2.y);
            }
        }
        int ss = s + 3;
        if (ss < 16) {
#pragma unroll
            for (int k = 0; k < 4; k++) {
                int row = r0 + 64 * k;
                int jc = j ^ (row & 3);
                cpa16(fsb + ((ss & 3) << 14) + row * 64 + jc * 16,
                      fbase + (size_t)row * Dd + ss * 16 + j * 4);
            }
        }
        cpcommit();
    }

    int n = c * 256 + tid;
    float rn;
    if (FIRST) {
        float2 sv = upk(sq);
        rn = 1.f / fmaxf(sqrtf(sv.x + sv.y), EPSC);
        g_rnorm[b * Nn + n] = rn;
    } else rn = g_rnorm[b * Nn + n];

    float sim[8];
#pragma unroll
    for (int p = 0; p < 8; p++) {
        float2 a = upk(acc[p]);
        sim[p] = (a.x + a.y) * rn;
    }
    float4* o = (float4*)(g_sim + ((size_t)b * Nn + n) * 8);
    o[0] = make_float4(sim[0], sim[1], sim[2], sim[3]);
    o[1] = make_float4(sim[4], sim[5], sim[6], sim[7]);

    float mv[8];
#pragma unroll
    for (int p = 0; p < 8; p++) mv[p] = sim[p];
    red8<true>(mv);
    __syncthreads();
    if (lane < 8) red[wid * 8 + lane] = mv[lane];
    __syncthreads();
    if (tid < 8) {
        float m = red[tid];
#pragma unroll
        for (int w = 1; w < 8; w++) m = fmaxf(m, red[w * 8 + tid]);
        atomicMax(&g_max[b * 8 + tid], f2ord(m));
    }

    if (DENS) {
        int a = g_idx[b * Nn + n];
        float dv[8];
#pragma unroll
        for (int p = 0; p < 8; p++) dv[p] = (p == a) ? sim[p] : 0.f;
        red8<false>(dv);
        __syncthreads();
        if (lane < 8) red[wid * 8 + lane] = dv[lane];
        __syncthreads();
        if (tid < 8) {
            float s2 = red[tid];
#pragma unroll
            for (int w = 1; w < 8; w++) s2 += red[w * 8 + tid];
            g_msum[((size_t)b * 16 + c) * 8 + tid] = s2;
        }
    }
}

// ---- stats: tau; exp in place; Z partials ----
template<bool HAS_TAU>
__global__ void __launch_bounds__(256) k_stats(int par) {
    int b = blockIdx.x >> 2, q = blockIdx.x & 3;
    int tid = threadIdx.x, lane = tid & 31, wid = tid >> 5;
    __shared__ float mxs[8], iss[8], red[64];
    if (tid < 8) {
        mxs[tid] = ord2f(g_max[b * 8 + tid]);
        float is;
        if (HAS_TAU) {
            float s = 0.f;
#pragma unroll
            for (int c = 0; c < 16; c++) s += g_msum[((size_t)b * 16 + c) * 8 + tid];
            int cnt = g_cnt[par][b * 8 + tid];
            float mean = s / (float)(cnt >= 1 ? cnt : 1);
            float dens = (cnt >= 1) ? (1.f - mean) : 1.f;
            is = 1.f / (0.1f * fmaxf(dens, 1e-10f));
        } else {
            is = 100.f;
        }
        iss[tid] = is;
    }
    __syncthreads();
    float z[8];
#pragma unroll
    for (int p = 0; p < 8; p++) z[p] = 0.f;
    for (int k = 0; k < 4; k++) {
        int n = q * 1024 + k * 256 + tid;
        float4* p4 = (float4*)(g_sim + ((size_t)b * Nn + n) * 8);
        float4 a = p4[0], c = p4[1];
        a.x = expf((a.x - mxs[0]) * iss[0]); z[0] += a.x;
        a.y = expf((a.y - mxs[1]) * iss[1]); z[1] += a.y;
        a.z = expf((a.z - mxs[2]) * iss[2]); z[2] += a.z;
        a.w = expf((a.w - mxs[3]) * iss[3]); z[3] += a.w;
        c.x = expf((c.x - mxs[4]) * iss[4]); z[4] += c.x;
        c.y = expf((c.y - mxs[5]) * iss[5]); z[5] += c.y;
        c.z = expf((c.z - mxs[6]) * iss[6]); z[6] += c.z;
        c.w = expf((c.w - mxs[7]) * iss[7]); z[7] += c.w;
        p4[0] = a; p4[1] = c;
    }
    red8<false>(z);
    if (lane < 8) red[wid * 8 + lane] = z[lane];
    __syncthreads();
    if (tid < 8) {
        float s = red[tid];
#pragma unroll
        for (int w = 1; w < 8; w++) s += red[w * 8 + tid];
        g_zpart[((size_t)b * 4 + q) * 8 + tid] = s;
    }
}

// ---- update v4 (unchanged from R9) ----
__global__ void __launch_bounds__(256) k_update(const float* __restrict__ feats,
                                                int parw) {
    int b = blockIdx.x >> 4, ch = blockIdx.x & 15;
    int tid = threadIdx.x, lane = tid & 31;
    __shared__ float ws[256];
    __shared__ int   bis[256];
    __shared__ u64   part[8][128];
    __shared__ float izs[8];

    u64 pol = mkpol_rt(b < PINB);
    if (tid < 8) {
        float z = 0.f;
#pragma unroll
        for (int q = 0; q < 4; q++) z += g_zpart[((size_t)b * 4 + q) * 8 + tid];
        izs[tid] = 1.f / z;
    }
    __syncthreads();

    int base = ch * 256;
    {
        const float4* sp = (const float4*)(g_sim + ((size_t)b * Nn + base + tid) * 8);
        float4 e0 = sp[0], e1 = sp[1];
        float w[8] = { e0.x * izs[0], e0.y * izs[1], e0.z * izs[2], e0.w * izs[3],
                       e1.x * izs[4], e1.y * izs[5], e1.z * izs[6], e1.w * izs[7] };
        int bi = 0; float bw = w[0];
#pragma unroll
        for (int p = 1; p < 8; p++) if (w[p] > bw) { bw = w[p]; bi = p; }
        g_idx[b * Nn + base + tid] = bi;
        ws[tid] = bw;
        bis[tid] = bi;
        int mycnt = 0;
#pragma unroll
        for (int p = 0; p < 8; p++) {
            unsigned mk = __ballot_sync(FULLW, bi == p);
            if (lane == p) mycnt += __popc(mk);
        }
        if (lane < 8) atomicAdd(&g_cnt[parw][b * 8 + lane], mycnt);
    }
    __syncthreads();

    int g2 = tid >> 7;
    int t = tid & 127;
    const float* fb = feats + ((size_t)b * Nn + base + g2 * 128) * Dd;

    u64 acc[8];
#pragma unroll
    for (int p = 0; p < 8; p++) acc[p] = 0ull;

    for (int r0 = 0; r0 < 128; r0 += 8) {
        u64 f[8];
#pragma unroll
        for (int k = 0; k < 8; k++)
            f[k] = ldg64h(fb + (size_t)(r0 + k) * Dd + 2 * t, pol);
#pragma unroll
        for (int k = 0; k < 8; k++) {
            int row = (g2 << 7) + r0 + k;
            float wv = ws[row];
            int bi = bis[row];
            u64 wp = pk(wv, wv);
            if (bi < 4) {
                if (bi < 2) { if (bi == 0) fma2(acc[0], wp, f[k]); else fma2(acc[1], wp, f[k]); }
                else        { if (bi == 2) fma2(acc[2], wp, f[k]); else fma2(acc[3], wp, f[k]); }
            } else {
                if (bi < 6) { if (bi == 4) fma2(acc[4], wp, f[k]); else fma2(acc[5], wp, f[k]); }
                else        { if (bi == 6) fma2(acc[6], wp, f[k]); else fma2(acc[7], wp, f[k]); }
            }
        }
    }

    if (g2 == 1) {
#pragma unroll
        for (int p = 0; p < 8; p++) part[p][t] = acc[p];
    }
    __syncthreads();
    if (g2 == 0) {
        float* op = g_ppart + ((size_t)(b * 16 + ch)) * 2048;
#pragma unroll
        for (int p = 0; p < 8; p++) {
            add2(acc[p], part[p][t]);
            float2 a = upk(acc[p]);
            *(float2*)(op + p * 256 + 2 * t) = a;
        }
    }
}

// ---- reduce 16 partials -> prototypes; normalize; reset state ----
__global__ void __launch_bounds__(256) k_reduce(float* __restrict__ outp, int parzero) {
    __shared__ float r8[8];
    int bp = blockIdx.x, b = bp >> 3, p = bp & 7;
    int tid = threadIdx.x;
    float v = 0.f;
#pragma unroll
    for (int c = 0; c < 16; c++)
        v += g_ppart[((size_t)(b * 16 + c)) * 2048 + p * 256 + tid];
    float ss = block_sum256(v * v, r8);
    float rn = 1.f / fmaxf(sqrtf(ss), EPSC);
    outp[(size_t)bp * Dd + tid] = v;
    g_pn[(size_t)bp * Dd + tid] = v * rn;
    if (tid == 0) { g_max[bp] = 0u; g_cnt[parzero][bp] = 0; }
}

// ---- final sim_map: cp.async ring, inline rnorm ----
__global__ void __launch_bounds__(256) k_simmap(const float* __restrict__ forg,
                                                float* __restrict__ out) {
    extern __shared__ char smraw[];
    float4* pn_s = (float4*)smraw;
    float*  fs   = (float*)(smraw + 8192);

    int b = blockIdx.x >> 4, c = blockIdx.x & 15;
    int tid = threadIdx.x;

    const float4* psrc = (const float4*)g_pn + (size_t)b * 512;
    for (int i = tid; i < 512; i += 256) pn_s[i] = psrc[i];

    const float* fbase = forg + (size_t)c * 256 * Dd;
    int r0 = tid >> 2, j = tid & 3;
    unsigned fsb = (unsigned)__cvta_generic_to_shared(fs);

#pragma unroll
    for (int s = 0; s < 3; s++) {
#pragma unroll
        for (int k = 0; k < 4; k++) {
            int row = r0 + 64 * k;
            int jc = j ^ (row & 3);
            cpa16(fsb + (s << 14) + row * 64 + jc * 16,
                  fbase + (size_t)row * Dd + s * 16 + j * 4);
        }
        cpcommit();
    }

    u64 acc[8];
#pragma unroll
    for (int p = 0; p < 8; p++) acc[p] = 0ull;
    u64 sq = 0ull;
    int sw = tid & 3;

    for (int s = 0; s < 16; s++) {
        cpwait2();
        __syncthreads();
        const float* fb = fs + ((s & 3) << 12);
#pragma unroll
        for (int jj = 0; jj < 4; jj++) {
            ulonglong2 f2 = *(const ulonglong2*)&fb[tid * 16 + ((jj ^ sw) << 2)];
            fma2(sq, f2.x, f2.x); fma2(sq, f2.y, f2.y);
#pragma unroll
            for (int p = 0; p < 8; p++) {
                ulonglong2 q2 = *(const ulonglong2*)(pn_s + p * 64 + s * 4 + jj);
                fma2(acc[p], f2.x, q2.x);
                fma2(acc[p], f2.y, q2.y);
            }
        }
        int ss = s + 3;
        if (ss < 16) {
#pragma unroll
            for (int k = 0; k < 4; k++) {
                int row = r0 + 64 * k;
                int jc = j ^ (row & 3);
                cpa16(fsb + ((ss & 3) << 14) + row * 64 + jc * 16,
                      fbase + (size_t)row * Dd + ss * 16 + j * 4);
            }
        }
        cpcommit();
    }

    int m = c * 256 + tid;
    float2 sv = upk(sq);
    float rn = 1.f / fmaxf(sqrtf(sv.x + sv.y), EPSC);
#pragma unroll
    for (int p = 0; p < 8; p++) {
        float2 a = upk(acc[p]);
        out[((size_t)b * Pp + p) * Mm + m] = (a.x + a.y) * rn;
    }
}

extern "C" void kernel_launch(void* const* d_in, const int* in_sizes, int n_in,
                              void* d_out, int out_size) {
    const float* protos = (const float*)d_in[0];
    const float* feats  = (const float*)d_in[1];
    const float* forg   = (const float*)d_in[2];
    float* out = (float*)d_out;

    cudaFuncSetAttribute(k_sim<true, false>,
                         cudaFuncAttributeMaxDynamicSharedMemorySize, SIMSMEM);
    cudaFuncSetAttribute(k_sim<false, true>,
                         cudaFuncAttributeMaxDynamicSharedMemorySize, SIMSMEM);
    cudaFuncSetAttribute(k_simmap,
                         cudaFuncAttributeMaxDynamicSharedMemorySize, SIMSMEM);

    k_norm0<<<BPc, 256>>>(protos);

    k_sim<true, false><<<Bb * 16, 256, SIMSMEM>>>(feats);
    k_stats<false><<<Bb * 4, 256>>>(0);
    k_update<<<Bb * 16, 256>>>(feats, 0);
    k_reduce<<<BPc, 256>>>(out, 1);

    for (int t = 1; t < 5; t++) {
        k_sim<false, true><<<Bb * 16, 256, SIMSMEM>>>(feats);
        k_stats<true><<<Bb * 4, 256>>>((t - 1) & 1);
        k_update<<<Bb * 16, 256>>>(feats, t & 1);
        k_reduce<<<BPc, 256>>>(out, (t + 1) & 1);
    }

    k_simmap<<<Bb * 16, 256, SIMSMEM>>>(forg, out + (size_t)BPc * Dd);
}